// round 12
// baseline (speedup 1.0000x reference)
#include <cuda_runtime.h>
#include <cuda_bf16.h>
#include <cstdint>

// FASTMultiHeadAttention R12: R11 core with W*V moved to bf16 m16n8k16:
//   - W A-frags built by packing each thread's OWN S-accumulator pairs into
//     bf16x2 (m16n8k16 A k-positions == C-layout col pairs) -> NO shuffles
//   - W split-2 bf16 (more precise than previous tf32 W), V split-2 bf16
//   - product = wh*vh + wl*vh + wh*vl (24 mma16 vs 16 mma8, zero SHFL)
// Score GEMMs (S = QK^T, P = QR^T) byte-identical to R11.
// B=1, H=8, N=2048, D=64, fp32 in/out, causal.

namespace {
constexpr int H = 8, N = 2048, D = 64;
constexpr int NT = 512;            // 16 warps: 4 wm x 4 wn

constexpr int BUFSZ = 12288;       // floats per buffer: K 4096 | R 4096 | V 4096
constexpr int RING  = 2 * BUFSZ;   // 24576
constexpr int PSTR  = 138;
constexpr int DENB  = RING + 64 * PSTR;      // 33408
constexpr int SMEM_FLOATS = DENB + 256;      // 33664
constexpr int SMEM_BYTES  = SMEM_FLOATS * 4; // 134656
constexpr int KSTR = 68;           // epilogue scratch stride
}

// fragment-packed operands (prepass outputs)
__device__ float4 g_qpack[262144];   // (h, mt128, c4, lane32) x {A1,A2}
__device__ float4 g_kpack[262144];   // (h, jb32, c4, col64, t4)  {b0k1,b1k1,b0k2,b1k2}
__device__ float4 g_rpack[32768];    // (db32, c4, row64, t4)
__device__ float4 g_vpack[262144];   // (h, jb32, wn4, nt8, lane32) bf16 {vh_b0,vh_b1,vl_b0,vl_b1}

__device__ __forceinline__ void mma16(float* c, const uint32_t* a, uint32_t b0, uint32_t b1)
{
    asm volatile(
        "mma.sync.aligned.m16n8k16.row.col.f32.bf16.bf16.f32 "
        "{%0,%1,%2,%3}, {%4,%5,%6,%7}, {%8,%9}, {%0,%1,%2,%3};"
        : "+f"(c[0]), "+f"(c[1]), "+f"(c[2]), "+f"(c[3])
        : "r"(a[0]), "r"(a[1]), "r"(a[2]), "r"(a[3]), "r"(b0), "r"(b1));
}

__device__ __forceinline__ void split_bf16(float x, uint16_t& hi, uint16_t& lo)
{
    __nv_bfloat16 b1 = __float2bfloat16_rn(x);
    float r = x - __bfloat162float(b1);
    __nv_bfloat16 b2 = __float2bfloat16_rn(r);
    hi = __bfloat16_as_ushort(b1);
    lo = __bfloat16_as_ushort(b2);
}

__device__ __forceinline__ uint32_t pk2(uint16_t lo_even, uint16_t hi_odd)
{
    return ((uint32_t)hi_odd << 16) | lo_even;
}

__device__ __forceinline__ void cp16(uint32_t s, const void* g)
{
    asm volatile("cp.async.cg.shared.global [%0], [%1], 16;" :: "r"(s), "l"(g));
}

// pack two f32 into bf16x2: low half = first arg (even-k), high = second (odd-k)
__device__ __forceinline__ uint32_t pack_bf16x2(float lo_even, float hi_odd)
{
    uint32_t d;
    asm("cvt.rn.bf16x2.f32 %0, %1, %2;" : "=r"(d) : "f"(hi_odd), "f"(lo_even));
    return d;
}

// ---------------- fused prepass: 2688 blocks x 256 ----------------
//   [0,512) Q  [512,1536) K  [1536,1664) R  [1664,2688) V

__global__ void __launch_bounds__(256)
pp_fused(const float* __restrict__ q, const float* __restrict__ k,
         const float* __restrict__ v, const float* __restrict__ rpe)
{
    const int bid = blockIdx.x;
    if (bid < 512) {
        int idx = bid * 256 + threadIdx.x;
        int lane = idx & 31, c = (idx >> 5) & 3, mt = (idx >> 7) & 127, h = idx >> 14;
        int g = lane >> 2, t4 = lane & 3;
        const float* qh = q + (size_t)h * N * D;
        int r0 = mt * 16 + g;
        int k0 = c * 16 + 2 * t4;
        float x[2][4];
        #pragma unroll
        for (int rr = 0; rr < 2; rr++) {
            const float* row = qh + (size_t)(r0 + 8 * rr) * D;
            x[rr][0] = row[k0];     x[rr][1] = row[k0 + 1];
            x[rr][2] = row[k0 + 8]; x[rr][3] = row[k0 + 9];
        }
        uint16_t hb[2][4], lb[2][4];
        #pragma unroll
        for (int rr = 0; rr < 2; rr++)
            #pragma unroll
            for (int e = 0; e < 4; e++) split_bf16(x[rr][e], hb[rr][e], lb[rr][e]);
        float4 A1, A2;
        A1.x = __uint_as_float(pk2(hb[0][0], hb[0][1]));
        A1.y = __uint_as_float(pk2(hb[1][0], hb[1][1]));
        A1.z = __uint_as_float(pk2(hb[0][2], hb[0][3]));
        A1.w = __uint_as_float(pk2(hb[1][2], hb[1][3]));
        A2.x = __uint_as_float(pk2(lb[0][0], lb[0][1]));
        A2.y = __uint_as_float(pk2(lb[1][0], lb[1][1]));
        A2.z = __uint_as_float(pk2(lb[0][2], lb[0][3]));
        A2.w = __uint_as_float(pk2(lb[1][2], lb[1][3]));
        g_qpack[idx * 2]     = A1;
        g_qpack[idx * 2 + 1] = A2;
    } else if (bid < 1536) {
        int idx = (bid - 512) * 256 + threadIdx.x;
        int t4 = idx & 3, col = (idx >> 2) & 63, c = (idx >> 8) & 3;
        int jb = (idx >> 10) & 31, h = idx >> 15;
        const float* row = k + ((size_t)h * N + jb * 64 + col) * D;
        int k0 = c * 16 + 2 * t4;
        float y0 = row[k0], y1 = row[k0 + 1], y2 = row[k0 + 8], y3 = row[k0 + 9];
        uint16_t h0, l0, h1, l1, h2, l2, h3, l3;
        split_bf16(y0, h0, l0); split_bf16(y1, h1, l1);
        split_bf16(y2, h2, l2); split_bf16(y3, h3, l3);
        float4 o;
        o.x = __uint_as_float(pk2(h0, h1));
        o.y = __uint_as_float(pk2(h2, h3));
        o.z = __uint_as_float(pk2(l0, l1));
        o.w = __uint_as_float(pk2(l2, l3));
        g_kpack[idx] = o;
    } else if (bid < 1664) {
        int idx = (bid - 1536) * 256 + threadIdx.x;
        int t4 = idx & 3, row = (idx >> 2) & 63, c = (idx >> 8) & 3, db = idx >> 10;
        int t = db * 64 + row;
        const float* src = rpe + (size_t)(t + N - 1) * D;
        int k0 = c * 16 + 2 * t4;
        float y0 = src[k0], y1 = src[k0 + 1], y2 = src[k0 + 8], y3 = src[k0 + 9];
        uint16_t h0, l0, h1, l1, h2, l2, h3, l3;
        split_bf16(y0, h0, l0); split_bf16(y1, h1, l1);
        split_bf16(y2, h2, l2); split_bf16(y3, h3, l3);
        float4 o;
        o.x = __uint_as_float(pk2(h0, h1));
        o.y = __uint_as_float(pk2(h2, h3));
        o.z = __uint_as_float(pk2(l0, l1));
        o.w = __uint_as_float(pk2(l2, l3));
        g_rpack[idx] = o;
    } else {
        // V pack: bf16 split-2 B-frags for m16n8k16.
        // (h, jb, wn, nt, lane): k = warp's 16 j's (16*wn + 2t4 pairs), n = d col 8nt+g
        int idx = (bid - 1664) * 256 + threadIdx.x;
        int lane = idx & 31, nt = (idx >> 5) & 7, wn = (idx >> 8) & 3;
        int jb = (idx >> 10) & 31, h = idx >> 15;
        int g = lane >> 2, t4 = lane & 3;
        const float* vh = v + (size_t)h * N * D;
        int j0 = jb * 64 + 16 * wn + 2 * t4;
        int d  = 8 * nt + g;
        float v00 = vh[(size_t)(j0)     * D + d];
        float v01 = vh[(size_t)(j0 + 1) * D + d];
        float v80 = vh[(size_t)(j0 + 8) * D + d];
        float v81 = vh[(size_t)(j0 + 9) * D + d];
        uint16_t h00, l00, h01, l01, h80, l80, h81, l81;
        split_bf16(v00, h00, l00); split_bf16(v01, h01, l01);
        split_bf16(v80, h80, l80); split_bf16(v81, h81, l81);
        float4 o;
        o.x = __uint_as_float(pk2(h00, h01));   // vh b0 (k 2t4, 2t4+1)
        o.y = __uint_as_float(pk2(h80, h81));   // vh b1 (k 2t4+8, 2t4+9)
        o.z = __uint_as_float(pk2(l00, l01));   // vl b0
        o.w = __uint_as_float(pk2(l80, l81));   // vl b1
        g_vpack[idx] = o;
    }
}

// ---------------- main kernel ----------------

__global__ void __launch_bounds__(NT, 1)
fastmax_bf16x2_kernel(float* __restrict__ out)
{
    extern __shared__ float sm[];
    uint32_t smb;
    asm("{.reg .u64 t; cvta.to.shared.u64 t, %1; cvt.u32.u64 %0, t;}"
        : "=r"(smb) : "l"(sm));

    const int tid  = threadIdx.x;
    const int lane = tid & 31;
    const int wid  = tid >> 5;
    const int g    = lane >> 2;
    const int t4   = lane & 3;
    const int wm   = wid & 3;
    const int wn   = wid >> 2;

    // 144-CTA balanced schedule: ib 28..31 solo, (27-p, p) pairs
    const int bx = blockIdx.x;
    int h, ib0, ib1, npass;
    if (bx < 32) {
        h = bx >> 2; ib0 = 28 + (bx & 3); ib1 = 0; npass = 1;
    } else {
        int c = bx - 32;
        h = c / 14;
        int p = c % 14;
        ib0 = 27 - p; ib1 = p; npass = 2;
    }

    float* sps = sm + RING;
    const int prow0 = 16 * wm + g;
    float* psrow0 = sps + prow0 * PSTR;
    float* psrow1 = sps + (prow0 + 8) * PSTR;
    float* op = out + (size_t)h * N * D;

    #pragma unroll 1
    for (int pass = 0; pass < npass; pass++) {
        const int ib = pass ? ib1 : ib0;
        const int i0 = ib * 64;

        // Q fragments (persistent in registers)
        uint32_t qa1[4][4], qa2[4][4];
        #pragma unroll
        for (int c = 0; c < 4; c++) {
            const float4* src = &g_qpack[(((size_t)(h * 128 + ib * 4 + wm) * 4 + c) * 32 + lane) * 2];
            float4 A1 = src[0], A2 = src[1];
            qa1[c][0] = __float_as_uint(A1.x); qa1[c][1] = __float_as_uint(A1.y);
            qa1[c][2] = __float_as_uint(A1.z); qa1[c][3] = __float_as_uint(A1.w);
            qa2[c][0] = __float_as_uint(A2.x); qa2[c][1] = __float_as_uint(A2.y);
            qa2[c][2] = __float_as_uint(A2.z); qa2[c][3] = __float_as_uint(A2.w);
        }

        float oacc[8][4];
        #pragma unroll
        for (int nt = 0; nt < 8; nt++)
            #pragma unroll
            for (int c = 0; c < 4; c++) oacc[nt][c] = 0.f;
        float den0 = 0.f, den1 = 0.f;

        // prefetch tile 0 (K + R + V) into buf 0
        {
            const float4* gk = g_kpack + (size_t)(h * 32 + ib) * 1024;
            const float4* gr = g_rpack;
            const float4* gv = g_vpack + (size_t)(h * 32 + ib) * 1024;
            for (int t = tid; t < 1024; t += NT) {
                cp16(smb + t * 16,         gk + t);
                cp16(smb + 16384 + t * 16, gr + t);
                cp16(smb + 32768 + t * 16, gv + t);
            }
            asm volatile("cp.async.commit_group;" ::: "memory");
        }

        for (int m = 0; m <= ib; m++) {
            asm volatile("cp.async.wait_group 0;" ::: "memory");
            __syncthreads();                        // buf[m&1] ready everywhere

            if (m < ib) {                           // prefetch next tile
                const int jb = ib - m - 1;
                const float4* gk = g_kpack + (size_t)(h * 32 + jb) * 1024;
                const float4* gr = g_rpack + (size_t)(m + 1) * 1024;
                const float4* gv = g_vpack + (size_t)(h * 32 + jb) * 1024;
                uint32_t sb = smb + ((m + 1) & 1) * (BUFSZ * 4);
                for (int t = tid; t < 1024; t += NT) {
                    cp16(sb + t * 16,         gk + t);
                    cp16(sb + 16384 + t * 16, gr + t);
                    cp16(sb + 32768 + t * 16, gv + t);
                }
                asm volatile("cp.async.commit_group;" ::: "memory");
            }

            const uint4* kb4 = (const uint4*)(sm + (m & 1) * BUFSZ);
            const uint4* rb4 = kb4 + 1024;
            const uint4* vb4 = (const uint4*)(sm + (m & 1) * BUFSZ + 8192);

            // ---- fused S = QK^T and P = QR^T (bf16x2: hh + lh + hl) ----
            float sacc[2][4], pacc[2][4];
            #pragma unroll
            for (int nt = 0; nt < 2; nt++)
                #pragma unroll
                for (int c = 0; c < 4; c++) { sacc[nt][c] = 0.f; pacc[nt][c] = 0.f; }

            #pragma unroll
            for (int c = 0; c < 4; c++) {
                #pragma unroll
                for (int nt = 0; nt < 2; nt++) {
                    int fi = (c * 64 + 16 * wn + 8 * nt + g) * 4 + t4;
                    uint4 kf = kb4[fi];
                    mma16(sacc[nt], qa1[c], kf.x, kf.y);
                    mma16(sacc[nt], qa2[c], kf.x, kf.y);
                    mma16(sacc[nt], qa1[c], kf.z, kf.w);
                    uint4 rfr = rb4[fi];
                    mma16(pacc[nt], qa1[c], rfr.x, rfr.y);
                    mma16(pacc[nt], qa2[c], rfr.x, rfr.y);
                    mma16(pacc[nt], qa1[c], rfr.z, rfr.w);
                }
            }

            // ---- P-new into wm-partitioned 128-slot ring ----
            {
                const int bslot = (64 * m) & 127;
                #pragma unroll
                for (int nt = 0; nt < 2; nt++) {
                    int dl = 16 * wn + 8 * nt + 2 * t4;
                    *(float2*)&psrow0[bslot + dl] = make_float2(pacc[nt][0], pacc[nt][1]);
                    *(float2*)&psrow1[bslot + dl] = make_float2(pacc[nt][2], pacc[nt][3]);
                }
            }
            // ring rows [16wm,16wm+16) produced/consumed only by this wm group
            asm volatile("bar.sync %0, %1;" :: "r"(1 + wm), "r"(128) : "memory");

            // ---- s += P gather; w = 1+s+s^2/2; causal; den from raw w ----
            float wf[2][4];
            #pragma unroll
            for (int nt = 0; nt < 2; nt++) {
                int colb = 16 * wn + 8 * nt + 2 * t4;
                #pragma unroll
                for (int c = 0; c < 4; c++) {
                    int row_l = prow0 + ((c >> 1) << 3);
                    int col_l = colb + (c & 1);
                    unsigned slot = (unsigned)(64 * m + row_l - col_l) & 127u;
                    float s = sacc[nt][c] + sps[row_l * PSTR + slot];
                    float w = fmaf(s, fmaf(s, 0.5f, 1.0f), 1.0f);
                    if (m == 0 && col_l > row_l) w = 0.0f;
                    wf[nt][c] = w;
                    if (c < 2) den0 += w;
                    else       den1 += w;
                }
            }

            // ---- W A-frags: pack own C-pairs as bf16x2 (split-2); NO shuffles ----
            // m16n8k16 A k-positions {2t4,2t4+1,2t4+8,2t4+9} == C-layout col pairs.
            uint32_t awh[4], awl[4];
            #pragma unroll
            for (int nt = 0; nt < 2; nt++) {
                #pragma unroll
                for (int half = 0; half < 2; half++) {       // rows g / g+8
                    float w0 = wf[nt][2 * half + 0];
                    float w1 = wf[nt][2 * half + 1];
                    uint32_t hh = pack_bf16x2(w0, w1);
                    float r0 = w0 - __uint_as_float(hh << 16);
                    float r1 = w1 - __uint_as_float(hh & 0xFFFF0000u);
                    awh[2 * nt + half] = hh;
                    awl[2 * nt + half] = pack_bf16x2(r0, r1);
                }
            }

            // ---- O += W x V: wh*vh + wl*vh + wh*vl (bf16 m16n8k16) ----
            #pragma unroll
            for (int nt = 0; nt < 8; nt++) {
                uint4 vf = vb4[(wn * 8 + nt) * 32 + lane];
                mma16(oacc[nt], awh, vf.x, vf.y);
                mma16(oacc[nt], awl, vf.x, vf.y);
                mma16(oacc[nt], awh, vf.z, vf.w);
            }
        }

        // ---- epilogue: den lane-reduce, combine 4 wn partials, write ----
        den0 += __shfl_xor_sync(0xffffffffu, den0, 1);
        den0 += __shfl_xor_sync(0xffffffffu, den0, 2);
        den1 += __shfl_xor_sync(0xffffffffu, den1, 1);
        den1 += __shfl_xor_sync(0xffffffffu, den1, 2);

        __syncthreads();                 // all smem reads of final tile done
        float* ob1  = sm;                // scratch over buffer region
        float* ob2  = sm + 4352;
        float* ob3  = sm + 8704;
        float* denb = sm + DENB;

        if (wn > 0) {
            float* ob = (wn == 1) ? ob1 : (wn == 2) ? ob2 : ob3;
            #pragma unroll
            for (int nt = 0; nt < 8; nt++) {
                int dcol = 8 * nt + 2 * t4;
                *(float2*)&ob[prow0 * KSTR + dcol]       = make_float2(oacc[nt][0], oacc[nt][1]);
                *(float2*)&ob[(prow0 + 8) * KSTR + dcol] = make_float2(oacc[nt][2], oacc[nt][3]);
            }
            if (t4 == 0) {
                denb[prow0 * 4 + wn]       = den0;
                denb[(prow0 + 8) * 4 + wn] = den1;
            }
        }
        __syncthreads();
        if (wn == 0) {
            float d0 = den0 + denb[prow0 * 4 + 1] + denb[prow0 * 4 + 2] + denb[prow0 * 4 + 3];
            float d1 = den1 + denb[(prow0 + 8) * 4 + 1] + denb[(prow0 + 8) * 4 + 2]
                            + denb[(prow0 + 8) * 4 + 3];
            float inv0 = 1.0f / d0;
            float inv1 = 1.0f / d1;
            #pragma unroll
            for (int nt = 0; nt < 8; nt++) {
                int dcol = 8 * nt + 2 * t4;
                float2 p1 = *(const float2*)&ob1[prow0 * KSTR + dcol];
                float2 p2 = *(const float2*)&ob2[prow0 * KSTR + dcol];
                float2 p3 = *(const float2*)&ob3[prow0 * KSTR + dcol];
                float2 q1 = *(const float2*)&ob1[(prow0 + 8) * KSTR + dcol];
                float2 q2 = *(const float2*)&ob2[(prow0 + 8) * KSTR + dcol];
                float2 q3 = *(const float2*)&ob3[(prow0 + 8) * KSTR + dcol];
                float2 o0 = make_float2((oacc[nt][0] + p1.x + p2.x + p3.x) * inv0,
                                        (oacc[nt][1] + p1.y + p2.y + p3.y) * inv0);
                float2 o1 = make_float2((oacc[nt][2] + q1.x + q2.x + q3.x) * inv1,
                                        (oacc[nt][3] + q1.y + q2.y + q3.y) * inv1);
                *(float2*)&op[(size_t)(i0 + prow0) * D + dcol]     = o0;
                *(float2*)&op[(size_t)(i0 + prow0 + 8) * D + dcol] = o1;
            }
        }
        __syncthreads();                 // scratch free before next pass prefetch
    }
}

extern "C" void kernel_launch(void* const* d_in, const int* in_sizes, int n_in,
                              void* d_out, int out_size)
{
    (void)in_sizes; (void)n_in; (void)out_size;
    const float* q   = (const float*)d_in[0];
    const float* k   = (const float*)d_in[1];
    const float* v   = (const float*)d_in[2];
    const float* rpe = (const float*)d_in[3];
    float* out = (float*)d_out;

    pp_fused<<<2688, 256>>>(q, k, v, rpe);

    cudaFuncSetAttribute(fastmax_bf16x2_kernel,
                         cudaFuncAttributeMaxDynamicSharedMemorySize, SMEM_BYTES);
    fastmax_bf16x2_kernel<<<144, NT, SMEM_BYTES>>>(out);
}

// round 13
// speedup vs baseline: 1.1782x; 1.1782x over previous
#include <cuda_runtime.h>
#include <cuda_bf16.h>
#include <cuda_fp16.h>
#include <cstdint>

// FASTMultiHeadAttention R13: score GEMMs identical to R11/R12 (bf16x2 split-2,
// fused S+P). W*V now single-term fp16 m16n8k16 (tf32-precision class):
//   - A-frags packed from each thread's OWN C-pairs (no shuffles, as R12)
//   - single term: 8 mma16 per warp-tile (vs R11 16 mma8 + 16 SHFL, R12 24 mma16)
//   - V stored fp16 -> buffer 40KB/tile, fewer fill ops, 4 LDS.128 per warp
// B=1, H=8, N=2048, D=64, fp32 in/out, causal.

namespace {
constexpr int H = 8, N = 2048, D = 64;
constexpr int NT = 512;            // 16 warps: 4 wm x 4 wn

constexpr int BUFSZ = 10240;       // floats per buffer: K 4096 | R 4096 | V(fp16) 2048
constexpr int RING  = 2 * BUFSZ;   // 20480
constexpr int PSTR  = 138;
constexpr int DENB  = RING + 64 * PSTR;      // 29312
constexpr int SMEM_FLOATS = DENB + 256;      // 29568
constexpr int SMEM_BYTES  = SMEM_FLOATS * 4; // 118272
constexpr int KSTR = 68;           // epilogue scratch stride
}

// fragment-packed operands (prepass outputs)
__device__ float4 g_qpack[262144];   // (h, mt128, c4, lane32) x {A1,A2}
__device__ float4 g_kpack[262144];   // (h, jb32, c4, col64, t4)  {b0k1,b1k1,b0k2,b1k2}
__device__ float4 g_rpack[32768];    // (db32, c4, row64, t4)
__device__ uint4  g_vpack[131072];   // (h, jb32, wn4, ntp4, lane32) fp16 {e.b0,e.b1,o.b0,o.b1}

__device__ __forceinline__ void mma16(float* c, const uint32_t* a, uint32_t b0, uint32_t b1)
{
    asm volatile(
        "mma.sync.aligned.m16n8k16.row.col.f32.bf16.bf16.f32 "
        "{%0,%1,%2,%3}, {%4,%5,%6,%7}, {%8,%9}, {%0,%1,%2,%3};"
        : "+f"(c[0]), "+f"(c[1]), "+f"(c[2]), "+f"(c[3])
        : "r"(a[0]), "r"(a[1]), "r"(a[2]), "r"(a[3]), "r"(b0), "r"(b1));
}

__device__ __forceinline__ void mma16h(float* c, const uint32_t* a, uint32_t b0, uint32_t b1)
{
    asm volatile(
        "mma.sync.aligned.m16n8k16.row.col.f32.f16.f16.f32 "
        "{%0,%1,%2,%3}, {%4,%5,%6,%7}, {%8,%9}, {%0,%1,%2,%3};"
        : "+f"(c[0]), "+f"(c[1]), "+f"(c[2]), "+f"(c[3])
        : "r"(a[0]), "r"(a[1]), "r"(a[2]), "r"(a[3]), "r"(b0), "r"(b1));
}

__device__ __forceinline__ void split_bf16(float x, uint16_t& hi, uint16_t& lo)
{
    __nv_bfloat16 b1 = __float2bfloat16_rn(x);
    float r = x - __bfloat162float(b1);
    __nv_bfloat16 b2 = __float2bfloat16_rn(r);
    hi = __bfloat16_as_ushort(b1);
    lo = __bfloat16_as_ushort(b2);
}

__device__ __forceinline__ uint32_t pk2(uint16_t lo_even, uint16_t hi_odd)
{
    return ((uint32_t)hi_odd << 16) | lo_even;
}

// pack two f32 into f16x2: low half = first arg (even-k), high = second (odd-k)
__device__ __forceinline__ uint32_t packh(float lo_even, float hi_odd)
{
    uint32_t d;
    asm("cvt.rn.f16x2.f32 %0, %1, %2;" : "=r"(d) : "f"(hi_odd), "f"(lo_even));
    return d;
}

__device__ __forceinline__ void cp16(uint32_t s, const void* g)
{
    asm volatile("cp.async.cg.shared.global [%0], [%1], 16;" :: "r"(s), "l"(g));
}

// ---------------- fused prepass: 2176 blocks x 256 ----------------
//   [0,512) Q  [512,1536) K  [1536,1664) R  [1664,2176) V

__global__ void __launch_bounds__(256)
pp_fused(const float* __restrict__ q, const float* __restrict__ k,
         const float* __restrict__ v, const float* __restrict__ rpe)
{
    const int bid = blockIdx.x;
    if (bid < 512) {
        int idx = bid * 256 + threadIdx.x;
        int lane = idx & 31, c = (idx >> 5) & 3, mt = (idx >> 7) & 127, h = idx >> 14;
        int g = lane >> 2, t4 = lane & 3;
        const float* qh = q + (size_t)h * N * D;
        int r0 = mt * 16 + g;
        int k0 = c * 16 + 2 * t4;
        float x[2][4];
        #pragma unroll
        for (int rr = 0; rr < 2; rr++) {
            const float* row = qh + (size_t)(r0 + 8 * rr) * D;
            x[rr][0] = row[k0];     x[rr][1] = row[k0 + 1];
            x[rr][2] = row[k0 + 8]; x[rr][3] = row[k0 + 9];
        }
        uint16_t hb[2][4], lb[2][4];
        #pragma unroll
        for (int rr = 0; rr < 2; rr++)
            #pragma unroll
            for (int e = 0; e < 4; e++) split_bf16(x[rr][e], hb[rr][e], lb[rr][e]);
        float4 A1, A2;
        A1.x = __uint_as_float(pk2(hb[0][0], hb[0][1]));
        A1.y = __uint_as_float(pk2(hb[1][0], hb[1][1]));
        A1.z = __uint_as_float(pk2(hb[0][2], hb[0][3]));
        A1.w = __uint_as_float(pk2(hb[1][2], hb[1][3]));
        A2.x = __uint_as_float(pk2(lb[0][0], lb[0][1]));
        A2.y = __uint_as_float(pk2(lb[1][0], lb[1][1]));
        A2.z = __uint_as_float(pk2(lb[0][2], lb[0][3]));
        A2.w = __uint_as_float(pk2(lb[1][2], lb[1][3]));
        g_qpack[idx * 2]     = A1;
        g_qpack[idx * 2 + 1] = A2;
    } else if (bid < 1536) {
        int idx = (bid - 512) * 256 + threadIdx.x;
        int t4 = idx & 3, col = (idx >> 2) & 63, c = (idx >> 8) & 3;
        int jb = (idx >> 10) & 31, h = idx >> 15;
        const float* row = k + ((size_t)h * N + jb * 64 + col) * D;
        int k0 = c * 16 + 2 * t4;
        float y0 = row[k0], y1 = row[k0 + 1], y2 = row[k0 + 8], y3 = row[k0 + 9];
        uint16_t h0, l0, h1, l1, h2, l2, h3, l3;
        split_bf16(y0, h0, l0); split_bf16(y1, h1, l1);
        split_bf16(y2, h2, l2); split_bf16(y3, h3, l3);
        float4 o;
        o.x = __uint_as_float(pk2(h0, h1));
        o.y = __uint_as_float(pk2(h2, h3));
        o.z = __uint_as_float(pk2(l0, l1));
        o.w = __uint_as_float(pk2(l2, l3));
        g_kpack[idx] = o;
    } else if (bid < 1664) {
        int idx = (bid - 1536) * 256 + threadIdx.x;
        int t4 = idx & 3, row = (idx >> 2) & 63, c = (idx >> 8) & 3, db = idx >> 10;
        int t = db * 64 + row;
        const float* src = rpe + (size_t)(t + N - 1) * D;
        int k0 = c * 16 + 2 * t4;
        float y0 = src[k0], y1 = src[k0 + 1], y2 = src[k0 + 8], y3 = src[k0 + 9];
        uint16_t h0, l0, h1, l1, h2, l2, h3, l3;
        split_bf16(y0, h0, l0); split_bf16(y1, h1, l1);
        split_bf16(y2, h2, l2); split_bf16(y3, h3, l3);
        float4 o;
        o.x = __uint_as_float(pk2(h0, h1));
        o.y = __uint_as_float(pk2(h2, h3));
        o.z = __uint_as_float(pk2(l0, l1));
        o.w = __uint_as_float(pk2(l2, l3));
        g_rpack[idx] = o;
    } else {
        // V pack: fp16 B-frags for m16n8k16 W*V.
        // (h, jb, wn4, ntp4, lane32): k rows = warp's 16 j's, n col d = 8*nt+g
        int idx = (bid - 1664) * 256 + threadIdx.x;
        int lane = idx & 31, ntp = (idx >> 5) & 3, wn = (idx >> 7) & 3;
        int jb = (idx >> 9) & 31, h = idx >> 14;
        int g = lane >> 2, t4 = lane & 3;
        const float* vh = v + (size_t)h * N * D;
        int j0 = jb * 64 + 16 * wn + 2 * t4;
        int de = 8 * (2 * ntp) + g;        // even nt col
        int dq = 8 * (2 * ntp + 1) + g;    // odd nt col
        uint4 o;
        o.x = packh(vh[(size_t)(j0)     * D + de], vh[(size_t)(j0 + 1) * D + de]);
        o.y = packh(vh[(size_t)(j0 + 8) * D + de], vh[(size_t)(j0 + 9) * D + de]);
        o.z = packh(vh[(size_t)(j0)     * D + dq], vh[(size_t)(j0 + 1) * D + dq]);
        o.w = packh(vh[(size_t)(j0 + 8) * D + dq], vh[(size_t)(j0 + 9) * D + dq]);
        g_vpack[idx] = o;
    }
}

// ---------------- main kernel ----------------

__global__ void __launch_bounds__(NT, 1)
fastmax_bf16x2_kernel(float* __restrict__ out)
{
    extern __shared__ float sm[];
    uint32_t smb;
    asm("{.reg .u64 t; cvta.to.shared.u64 t, %1; cvt.u32.u64 %0, t;}"
        : "=r"(smb) : "l"(sm));

    const int tid  = threadIdx.x;
    const int lane = tid & 31;
    const int wid  = tid >> 5;
    const int g    = lane >> 2;
    const int t4   = lane & 3;
    const int wm   = wid & 3;
    const int wn   = wid >> 2;

    // 144-CTA balanced schedule: ib 28..31 solo, (27-p, p) pairs
    const int bx = blockIdx.x;
    int h, ib0, ib1, npass;
    if (bx < 32) {
        h = bx >> 2; ib0 = 28 + (bx & 3); ib1 = 0; npass = 1;
    } else {
        int c = bx - 32;
        h = c / 14;
        int p = c % 14;
        ib0 = 27 - p; ib1 = p; npass = 2;
    }

    float* sps = sm + RING;
    const int prow0 = 16 * wm + g;
    float* psrow0 = sps + prow0 * PSTR;
    float* psrow1 = sps + (prow0 + 8) * PSTR;
    float* op = out + (size_t)h * N * D;

    #pragma unroll 1
    for (int pass = 0; pass < npass; pass++) {
        const int ib = pass ? ib1 : ib0;
        const int i0 = ib * 64;

        // Q fragments (persistent in registers)
        uint32_t qa1[4][4], qa2[4][4];
        #pragma unroll
        for (int c = 0; c < 4; c++) {
            const float4* src = &g_qpack[(((size_t)(h * 128 + ib * 4 + wm) * 4 + c) * 32 + lane) * 2];
            float4 A1 = src[0], A2 = src[1];
            qa1[c][0] = __float_as_uint(A1.x); qa1[c][1] = __float_as_uint(A1.y);
            qa1[c][2] = __float_as_uint(A1.z); qa1[c][3] = __float_as_uint(A1.w);
            qa2[c][0] = __float_as_uint(A2.x); qa2[c][1] = __float_as_uint(A2.y);
            qa2[c][2] = __float_as_uint(A2.z); qa2[c][3] = __float_as_uint(A2.w);
        }

        float oacc[8][4];
        #pragma unroll
        for (int nt = 0; nt < 8; nt++)
            #pragma unroll
            for (int c = 0; c < 4; c++) oacc[nt][c] = 0.f;
        float den0 = 0.f, den1 = 0.f;

        // prefetch tile 0 (K + R + V) into buf 0
        {
            const float4* gk = g_kpack + (size_t)(h * 32 + ib) * 1024;
            const float4* gr = g_rpack;
            const uint4*  gv = g_vpack + (size_t)(h * 32 + ib) * 512;
            for (int t = tid; t < 1024; t += NT) {
                cp16(smb + t * 16,         gk + t);
                cp16(smb + 16384 + t * 16, gr + t);
                if (t < 512) cp16(smb + 32768 + t * 16, gv + t);
            }
            asm volatile("cp.async.commit_group;" ::: "memory");
        }

        for (int m = 0; m <= ib; m++) {
            asm volatile("cp.async.wait_group 0;" ::: "memory");
            __syncthreads();                        // buf[m&1] ready everywhere

            if (m < ib) {                           // prefetch next tile
                const int jb = ib - m - 1;
                const float4* gk = g_kpack + (size_t)(h * 32 + jb) * 1024;
                const float4* gr = g_rpack + (size_t)(m + 1) * 1024;
                const uint4*  gv = g_vpack + (size_t)(h * 32 + jb) * 512;
                uint32_t sb = smb + ((m + 1) & 1) * (BUFSZ * 4);
                for (int t = tid; t < 1024; t += NT) {
                    cp16(sb + t * 16,         gk + t);
                    cp16(sb + 16384 + t * 16, gr + t);
                    if (t < 512) cp16(sb + 32768 + t * 16, gv + t);
                }
                asm volatile("cp.async.commit_group;" ::: "memory");
            }

            const uint4* kb4 = (const uint4*)(sm + (m & 1) * BUFSZ);
            const uint4* rb4 = kb4 + 1024;
            const uint4* vb4 = (const uint4*)(sm + (m & 1) * BUFSZ + 8192);

            // ---- fused S = QK^T and P = QR^T (bf16x2: hh + lh + hl) ----
            float sacc[2][4], pacc[2][4];
            #pragma unroll
            for (int nt = 0; nt < 2; nt++)
                #pragma unroll
                for (int c = 0; c < 4; c++) { sacc[nt][c] = 0.f; pacc[nt][c] = 0.f; }

            #pragma unroll
            for (int c = 0; c < 4; c++) {
                #pragma unroll
                for (int nt = 0; nt < 2; nt++) {
                    int fi = (c * 64 + 16 * wn + 8 * nt + g) * 4 + t4;
                    uint4 kf = kb4[fi];
                    mma16(sacc[nt], qa1[c], kf.x, kf.y);
                    mma16(sacc[nt], qa2[c], kf.x, kf.y);
                    mma16(sacc[nt], qa1[c], kf.z, kf.w);
                    uint4 rfr = rb4[fi];
                    mma16(pacc[nt], qa1[c], rfr.x, rfr.y);
                    mma16(pacc[nt], qa2[c], rfr.x, rfr.y);
                    mma16(pacc[nt], qa1[c], rfr.z, rfr.w);
                }
            }

            // ---- P-new into wm-partitioned 128-slot ring ----
            {
                const int bslot = (64 * m) & 127;
                #pragma unroll
                for (int nt = 0; nt < 2; nt++) {
                    int dl = 16 * wn + 8 * nt + 2 * t4;
                    *(float2*)&psrow0[bslot + dl] = make_float2(pacc[nt][0], pacc[nt][1]);
                    *(float2*)&psrow1[bslot + dl] = make_float2(pacc[nt][2], pacc[nt][3]);
                }
            }
            // ring rows [16wm,16wm+16) produced/consumed only by this wm group
            asm volatile("bar.sync %0, %1;" :: "r"(1 + wm), "r"(128) : "memory");

            // ---- s += P gather; w = 1+s+s^2/2; causal; den accumulate ----
            float wf[2][4];
            #pragma unroll
            for (int nt = 0; nt < 2; nt++) {
                int colb = 16 * wn + 8 * nt + 2 * t4;
                #pragma unroll
                for (int c = 0; c < 4; c++) {
                    int row_l = prow0 + ((c >> 1) << 3);
                    int col_l = colb + (c & 1);
                    unsigned slot = (unsigned)(64 * m + row_l - col_l) & 127u;
                    float s = sacc[nt][c] + sps[row_l * PSTR + slot];
                    float w = fmaf(s, fmaf(s, 0.5f, 1.0f), 1.0f);
                    if (m == 0 && col_l > row_l) w = 0.0f;
                    wf[nt][c] = w;
                    if (c < 2) den0 += w;
                    else       den1 += w;
                }
            }

            // ---- W A-frags: pack own C-pairs as f16x2; NO shuffles ----
            // m16n8k16 A k-positions {2t4,2t4+1,2t4+8,2t4+9} == C-layout col pairs
            uint32_t aw[4];
            aw[0] = packh(wf[0][0], wf[0][1]);   // row g,   k 2t4..2t4+1
            aw[1] = packh(wf[0][2], wf[0][3]);   // row g+8, k 2t4..2t4+1
            aw[2] = packh(wf[1][0], wf[1][1]);   // row g,   k 2t4+8..+9
            aw[3] = packh(wf[1][2], wf[1][3]);   // row g+8, k 2t4+8..+9

            // ---- O += W x V (single-term fp16 m16n8k16; 8 mma) ----
            #pragma unroll
            for (int ntp = 0; ntp < 4; ntp++) {
                uint4 vf = vb4[(wn * 4 + ntp) * 32 + lane];
                mma16h(oacc[2 * ntp],     aw, vf.x, vf.y);
                mma16h(oacc[2 * ntp + 1], aw, vf.z, vf.w);
            }
        }

        // ---- epilogue: den lane-reduce, combine 4 wn partials, write ----
        den0 += __shfl_xor_sync(0xffffffffu, den0, 1);
        den0 += __shfl_xor_sync(0xffffffffu, den0, 2);
        den1 += __shfl_xor_sync(0xffffffffu, den1, 1);
        den1 += __shfl_xor_sync(0xffffffffu, den1, 2);

        __syncthreads();                 // all smem reads of final tile done
        float* ob1  = sm;                // scratch over buffer region
        float* ob2  = sm + 4352;
        float* ob3  = sm + 8704;
        float* denb = sm + DENB;

        if (wn > 0) {
            float* ob = (wn == 1) ? ob1 : (wn == 2) ? ob2 : ob3;
            #pragma unroll
            for (int nt = 0; nt < 8; nt++) {
                int dcol = 8 * nt + 2 * t4;
                *(float2*)&ob[prow0 * KSTR + dcol]       = make_float2(oacc[nt][0], oacc[nt][1]);
                *(float2*)&ob[(prow0 + 8) * KSTR + dcol] = make_float2(oacc[nt][2], oacc[nt][3]);
            }
            if (t4 == 0) {
                denb[prow0 * 4 + wn]       = den0;
                denb[(prow0 + 8) * 4 + wn] = den1;
            }
        }
        __syncthreads();
        if (wn == 0) {
            float d0 = den0 + denb[prow0 * 4 + 1] + denb[prow0 * 4 + 2] + denb[prow0 * 4 + 3];
            float d1 = den1 + denb[(prow0 + 8) * 4 + 1] + denb[(prow0 + 8) * 4 + 2]
                            + denb[(prow0 + 8) * 4 + 3];
            float inv0 = 1.0f / d0;
            float inv1 = 1.0f / d1;
            #pragma unroll
            for (int nt = 0; nt < 8; nt++) {
                int dcol = 8 * nt + 2 * t4;
                float2 p1 = *(const float2*)&ob1[prow0 * KSTR + dcol];
                float2 p2 = *(const float2*)&ob2[prow0 * KSTR + dcol];
                float2 p3 = *(const float2*)&ob3[prow0 * KSTR + dcol];
                float2 q1 = *(const float2*)&ob1[(prow0 + 8) * KSTR + dcol];
                float2 q2 = *(const float2*)&ob2[(prow0 + 8) * KSTR + dcol];
                float2 q3 = *(const float2*)&ob3[(prow0 + 8) * KSTR + dcol];
                float2 o0 = make_float2((oacc[nt][0] + p1.x + p2.x + p3.x) * inv0,
                                        (oacc[nt][1] + p1.y + p2.y + p3.y) * inv0);
                float2 o1 = make_float2((oacc[nt][2] + q1.x + q2.x + q3.x) * inv1,
                                        (oacc[nt][3] + q1.y + q2.y + q3.y) * inv1);
                *(float2*)&op[(size_t)(i0 + prow0) * D + dcol]     = o0;
                *(float2*)&op[(size_t)(i0 + prow0 + 8) * D + dcol] = o1;
            }
        }
        __syncthreads();                 // scratch free before next pass prefetch
    }
}

extern "C" void kernel_launch(void* const* d_in, const int* in_sizes, int n_in,
                              void* d_out, int out_size)
{
    (void)in_sizes; (void)n_in; (void)out_size;
    const float* q   = (const float*)d_in[0];
    const float* k   = (const float*)d_in[1];
    const float* v   = (const float*)d_in[2];
    const float* rpe = (const float*)d_in[3];
    float* out = (float*)d_out;

    pp_fused<<<2176, 256>>>(q, k, v, rpe);

    cudaFuncSetAttribute(fastmax_bf16x2_kernel,
                         cudaFuncAttributeMaxDynamicSharedMemorySize, SMEM_BYTES);
    fastmax_bf16x2_kernel<<<144, NT, SMEM_BYTES>>>(out);
}